// round 4
// baseline (speedup 1.0000x reference)
#include <cuda_runtime.h>

#define S 64
#define D 524288            // 512*32*32
#define DQ (D / 4)          // 131072 float4 columns per row

// ---- pass 1 tiling ----
#define P1_THREADS 256
#define P1_CCHUNKS (DQ / P1_THREADS)   // 512
#define P1_SGROUPS 8

// ---- pass 3 tiling ----
#define P3_THREADS 256
#define P3_COLS    512
#define P3_CCHUNKS (DQ / P3_COLS)   // 256
#define P3_STILE   16
#define P3_SGROUPS (S / P3_STILE)   // 4

// scratch (no device allocations allowed)
// g_part[p * 512 + cx]; p = k*8+sg, k<8 -> N[sg*8+k], k>=8 -> A[sg*8+k-8]
__device__ float g_part[128 * P1_CCHUNKS];
__device__ float g_coeff[3 * S];            // [cp(64)][cc(64)][cn(64)]

__device__ __forceinline__ float dot4(float4 a, float4 b) {
    return a.x * b.x + a.y * b.y + a.z * b.z + a.w * b.w;
}

// Pass 1: block = (col chunk cx, s-group sg). One float4 column per thread,
// 9 rows front-batched (MLP=9, 36 regs -> high occupancy). The 16 partial
// sums are reduced via a conflict-free smem transpose (16 STS + 16 LDS +
// 1 SHFL per thread) instead of an 80-SHFL butterfly.
__global__ __launch_bounds__(P1_THREADS) void dots_kernel(const float4* __restrict__ q4) {
    const int sg  = blockIdx.y;
    const int s0  = sg * 8;
    const int col = blockIdx.x * P1_THREADS + threadIdx.x;

    float4 r[9];
#pragma unroll
    for (int k = 0; k < 9; k++) {
        int row = s0 + k;
        if (row > S - 1) row = S - 1;   // sg==7 halo; its A[63] is never read
        r[k] = q4[(size_t)row * DQ + col];
    }

    float v[16];
#pragma unroll
    for (int k = 0; k < 8; k++) {
        v[k]     = dot4(r[k], r[k]);        // N[s0+k]
        v[k + 8] = dot4(r[k], r[k + 1]);    // A[s0+k]
    }

    // transpose into smem: row k padded to 257 floats -> both phases conflict-free
    __shared__ float sh[16][P1_THREADS + 1];
#pragma unroll
    for (int k = 0; k < 16; k++) sh[k][threadIdx.x] = v[k];
    __syncthreads();

    // stage 1: thread t sums 16 entries of value k = t%16, segment seg = t/16
    const int k   = threadIdx.x & 15;
    const int seg = threadIdx.x >> 4;
    float acc = 0.f;
#pragma unroll
    for (int j = 0; j < 16; j++) acc += sh[k][seg * 16 + j];

    // lanes L and L^16 hold the same k, adjacent segments -> one shfl combines
    acc += __shfl_xor_sync(0xFFFFFFFFu, acc, 16);

    __shared__ float sh2[16][9];
    const int w = threadIdx.x >> 5;
    if ((threadIdx.x & 16) == 0)            // lanes 0-15 of each warp
        sh2[k][w] = acc;
    __syncthreads();

    if (threadIdx.x < 16) {
        float sum = 0.f;
#pragma unroll
        for (int j = 0; j < 8; j++) sum += sh2[threadIdx.x][j];
        g_part[(threadIdx.x * 8 + sg) * P1_CCHUNKS + blockIdx.x] = sum;
    }
}

// Pass 2 (tiny): coalesced warp-per-target reduction of the 512 partials,
// then entropy branch ladder + softmax-of-2 -> per-slice (cp, cc, cn).
__global__ void coeff_kernel(const float* __restrict__ ent) {
    __shared__ float sums[128];
    const int w    = threadIdx.x >> 5;   // 8 warps
    const int lane = threadIdx.x & 31;

#pragma unroll
    for (int j = 0; j < 16; j++) {
        const int p = w + 8 * j;
        const float* src = g_part + (size_t)p * P1_CCHUNKS;
        float acc = 0.f;
#pragma unroll
        for (int m = 0; m < P1_CCHUNKS / 32; m++)
            acc += src[lane + 32 * m];
#pragma unroll
        for (int off = 16; off > 0; off >>= 1)
            acc += __shfl_xor_sync(0xFFFFFFFFu, acc, off);
        if (lane == 0) sums[p] = acc;
    }
    __syncthreads();

    const int s = threadIdx.x;
    if (s >= S) return;

    // N[s] at p = (s&7)*8 + (s>>3); A[s] at p + 64
    const int pN = (s & 7) * 8 + (s >> 3);
    __shared__ float shN[S], shA[S];
    shN[s] = sums[pN];
    shA[s] = sums[pN + 64];
    __syncthreads();

    int k1, k2;
    if (s == 0) {
        const int b0 = (ent[0] >= ent[1]) ? 1 : 0;
        k1 = b0; k2 = b0;
    } else if (s == S - 1) {
        const int bL = (ent[S - 1] >= ent[S - 2]) ? (S - 2) : (S - 1);
        k1 = bL; k2 = bL;
    } else {
        const float e  = ent[s];
        const float ep = ent[s - 1];
        const float en = ent[s + 1];
        const bool ge_next = e >= en, ge_prev = e >= ep;
        const bool le_next = e <= en, le_prev = e <= ep;
        if (ge_next && ge_prev)      { k1 = s - 1; k2 = s + 1; }
        else if (le_next && ge_prev) { k1 = s - 1; k2 = s;     }
        else if (ge_next && le_prev) { k1 = s;     k2 = s + 1; }
        else                         { k1 = s;     k2 = s;     }
    }

    const float d1 = (k1 == s) ? shN[s] : ((k1 == s - 1) ? shA[s - 1] : shA[s]);
    const float d2 = (k2 == s) ? shN[s] : ((k2 == s - 1) ? shA[s - 1] : shA[s]);

    const float scale = rsqrtf((float)D);
    const float s1 = d1 * scale, s2 = d2 * scale;
    const float m  = fmaxf(s1, s2);
    float w1 = expf(s1 - m), w2 = expf(s2 - m);
    const float inv = 1.f / (w1 + w2);
    w1 *= inv; w2 *= inv;

    float cp = 0.f, cc = 0.f, cn = 0.f;
    if (k1 == s - 1) cp += w1; else if (k1 == s) cc += w1; else cn += w1;
    if (k2 == s - 1) cp += w2; else if (k2 == s) cc += w2; else cn += w2;

    g_coeff[s]       = cp;
    g_coeff[64 + s]  = cc;
    g_coeff[128 + s] = cn;
}

// Pass 3: out[s] = cp[s]*q[s-1] + cc[s]*q[s] + cn[s]*q[s+1].
// Column chunks processed in REVERSE order (L2 boomerang vs dots' stream)
// and output written with streaming stores (evict-first).
__global__ __launch_bounds__(P3_THREADS) void out_kernel(const float4* __restrict__ q4,
                                                         float4* __restrict__ o4) {
    __shared__ float scp[S], scc[S], scn[S];
    const int t = threadIdx.x;
    if (t < S) {
        scp[t] = g_coeff[t];
        scc[t] = g_coeff[64 + t];
        scn[t] = g_coeff[128 + t];
    }
    __syncthreads();

    const int cx = (P3_CCHUNKS - 1) - blockIdx.x;   // boomerang order
    const int st = blockIdx.y * P3_STILE;
    const int j0 = cx * P3_COLS + t;
    const int j1 = j0 + P3_THREADS;

    const int rprev = (st > 0) ? (st - 1) : 0;
    float4 a0 = q4[(size_t)rprev * DQ + j0];
    float4 a1 = q4[(size_t)rprev * DQ + j1];
    float4 b0 = q4[(size_t)st * DQ + j0];
    float4 b1 = q4[(size_t)st * DQ + j1];

#pragma unroll
    for (int i = 0; i < P3_STILE; i++) {
        const int s = st + i;
        const int rnext = (s + 1 < S) ? (s + 1) : (S - 1);
        float4 c0 = q4[(size_t)rnext * DQ + j0];
        float4 c1 = q4[(size_t)rnext * DQ + j1];

        const float cp = scp[s], cc = scc[s], cn = scn[s];

        float4 o0, o1;
        o0.x = cp * a0.x + cc * b0.x + cn * c0.x;
        o0.y = cp * a0.y + cc * b0.y + cn * c0.y;
        o0.z = cp * a0.z + cc * b0.z + cn * c0.z;
        o0.w = cp * a0.w + cc * b0.w + cn * c0.w;
        o1.x = cp * a1.x + cc * b1.x + cn * c1.x;
        o1.y = cp * a1.y + cc * b1.y + cn * c1.y;
        o1.z = cp * a1.z + cc * b1.z + cn * c1.z;
        o1.w = cp * a1.w + cc * b1.w + cn * c1.w;

        __stcs(&o4[(size_t)s * DQ + j0], o0);
        __stcs(&o4[(size_t)s * DQ + j1], o1);

        a0 = b0; b0 = c0;
        a1 = b1; b1 = c1;
    }
}

extern "C" void kernel_launch(void* const* d_in, const int* in_sizes, int n_in,
                              void* d_out, int out_size) {
    const float4* q4  = (const float4*)d_in[0];
    const float*  ent = (const float*)d_in[1];
    float4*       o4  = (float4*)d_out;

    dots_kernel<<<dim3(P1_CCHUNKS, P1_SGROUPS), P1_THREADS>>>(q4);
    coeff_kernel<<<1, 256>>>(ent);
    out_kernel<<<dim3(P3_CCHUNKS, P3_SGROUPS), P3_THREADS>>>(q4, o4);
}

// round 8
// speedup vs baseline: 1.0818x; 1.0818x over previous
#include <cuda_runtime.h>

#define S 64
#define D 524288            // 512*32*32
#define DQ (D / 4)          // 131072 float4 columns per row

// ---- shared tiling: 256 float4 columns x 8-row group ----
#define TB_THREADS 256
#define CCHUNKS (DQ / TB_THREADS)   // 512
#define SGROUPS 8
#define NTILES (CCHUNKS * SGROUPS)  // 4096

// scratch (no device allocations allowed)
// g_part[p * 512 + cx]; p = k*8+sg, k<8 -> N[sg*8+k], k>=8 -> A[sg*8+k-8]
__device__ float g_part[128 * CCHUNKS];
__device__ float g_coeff[3 * S];            // [cp(64)][cc(64)][cn(64)]

__device__ __forceinline__ float dot4(float4 a, float4 b) {
    return a.x * b.x + a.y * b.y + a.z * b.z + a.w * b.w;
}

// Pass 1: block = (col chunk cx, s-group sg). One float4 column per thread,
// 9 rows front-batched (MLP=9). 16 partials reduced via conflict-free smem
// transpose (16 STS + 16 LDS + 1 SHFL per thread).
__global__ __launch_bounds__(TB_THREADS) void dots_kernel(const float4* __restrict__ q4) {
    const int sg  = blockIdx.y;
    const int s0  = sg * 8;
    const int col = blockIdx.x * TB_THREADS + threadIdx.x;

    float4 r[9];
#pragma unroll
    for (int k = 0; k < 9; k++) {
        int row = s0 + k;
        if (row > S - 1) row = S - 1;   // sg==7 halo; its A[63] is never read
        r[k] = q4[(size_t)row * DQ + col];
    }

    float v[16];
#pragma unroll
    for (int k = 0; k < 8; k++) {
        v[k]     = dot4(r[k], r[k]);        // N[s0+k]
        v[k + 8] = dot4(r[k], r[k + 1]);    // A[s0+k]
    }

    __shared__ float sh[16][TB_THREADS + 1];
#pragma unroll
    for (int k = 0; k < 16; k++) sh[k][threadIdx.x] = v[k];
    __syncthreads();

    const int k   = threadIdx.x & 15;
    const int seg = threadIdx.x >> 4;
    float acc = 0.f;
#pragma unroll
    for (int j = 0; j < 16; j++) acc += sh[k][seg * 16 + j];
    acc += __shfl_xor_sync(0xFFFFFFFFu, acc, 16);

    __shared__ float sh2[16][9];
    const int w = threadIdx.x >> 5;
    if ((threadIdx.x & 16) == 0)
        sh2[k][w] = acc;
    __syncthreads();

    if (threadIdx.x < 16) {
        float sum = 0.f;
#pragma unroll
        for (int j = 0; j < 8; j++) sum += sh2[threadIdx.x][j];
        g_part[(threadIdx.x * 8 + sg) * CCHUNKS + blockIdx.x] = sum;
    }
}

// Pass 2 (tiny): coalesced warp-per-target reduction of the 512 partials,
// then entropy branch ladder + softmax-of-2 -> per-slice (cp, cc, cn).
__global__ void coeff_kernel(const float* __restrict__ ent) {
    __shared__ float sums[128];
    const int w    = threadIdx.x >> 5;   // 8 warps
    const int lane = threadIdx.x & 31;

#pragma unroll
    for (int j = 0; j < 16; j++) {
        const int p = w + 8 * j;
        const float* src = g_part + (size_t)p * CCHUNKS;
        float acc = 0.f;
#pragma unroll
        for (int m = 0; m < CCHUNKS / 32; m++)
            acc += src[lane + 32 * m];
#pragma unroll
        for (int off = 16; off > 0; off >>= 1)
            acc += __shfl_xor_sync(0xFFFFFFFFu, acc, off);
        if (lane == 0) sums[p] = acc;
    }
    __syncthreads();

    const int s = threadIdx.x;
    if (s >= S) return;

    const int pN = (s & 7) * 8 + (s >> 3);
    __shared__ float shN[S], shA[S];
    shN[s] = sums[pN];
    shA[s] = sums[pN + 64];
    __syncthreads();

    int k1, k2;
    if (s == 0) {
        const int b0 = (ent[0] >= ent[1]) ? 1 : 0;
        k1 = b0; k2 = b0;
    } else if (s == S - 1) {
        const int bL = (ent[S - 1] >= ent[S - 2]) ? (S - 2) : (S - 1);
        k1 = bL; k2 = bL;
    } else {
        const float e  = ent[s];
        const float ep = ent[s - 1];
        const float en = ent[s + 1];
        const bool ge_next = e >= en, ge_prev = e >= ep;
        const bool le_next = e <= en, le_prev = e <= ep;
        if (ge_next && ge_prev)      { k1 = s - 1; k2 = s + 1; }
        else if (le_next && ge_prev) { k1 = s - 1; k2 = s;     }
        else if (ge_next && le_prev) { k1 = s;     k2 = s + 1; }
        else                         { k1 = s;     k2 = s;     }
    }

    const float d1 = (k1 == s) ? shN[s] : ((k1 == s - 1) ? shA[s - 1] : shA[s]);
    const float d2 = (k2 == s) ? shN[s] : ((k2 == s - 1) ? shA[s - 1] : shA[s]);

    const float scale = rsqrtf((float)D);
    const float s1 = d1 * scale, s2 = d2 * scale;
    const float m  = fmaxf(s1, s2);
    float w1 = expf(s1 - m), w2 = expf(s2 - m);
    const float inv = 1.f / (w1 + w2);
    w1 *= inv; w2 *= inv;

    float cp = 0.f, cc = 0.f, cn = 0.f;
    if (k1 == s - 1) cp += w1; else if (k1 == s) cc += w1; else cn += w1;
    if (k2 == s - 1) cp += w2; else if (k2 == s) cc += w2; else cn += w2;

    g_coeff[s]       = cp;
    g_coeff[64 + s]  = cc;
    g_coeff[128 + s] = cn;
}

// Pass 3: out[s] = cp[s]*q[s-1] + cc[s]*q[s] + cn[s]*q[s+1].
// SAME tile decomposition as dots_kernel (256 cols x 8-row group), walked in
// EXACT REVERSE linearized block order so reads consume the L2 LRU stream
// dots left behind newest-first. Each thread preloads 10 rows (MLP=10),
// emits 8 output rows with streaming stores (evict-first).
__global__ __launch_bounds__(TB_THREADS) void out_kernel(const float4* __restrict__ q4,
                                                         float4* __restrict__ o4) {
    // reverse-linearized tile index
    const int rb = (NTILES - 1) - (blockIdx.x + (int)gridDim.x * blockIdx.y);
    const int cx = rb & (CCHUNKS - 1);
    const int sg = rb >> 9;             // rb / CCHUNKS
    const int s0 = sg * 8;
    const int col = cx * TB_THREADS + threadIdx.x;

    __shared__ float scp[8], scc[8], scn[8];
    if (threadIdx.x < 8) {
        scp[threadIdx.x] = g_coeff[s0 + threadIdx.x];
        scc[threadIdx.x] = g_coeff[64 + s0 + threadIdx.x];
        scn[threadIdx.x] = g_coeff[128 + s0 + threadIdx.x];
    }
    __syncthreads();

    // rows s0-1 .. s0+8, clamped; clamped halos are multiplied by zero coeffs
    float4 r[10];
#pragma unroll
    for (int k = 0; k < 10; k++) {
        int row = s0 - 1 + k;
        if (row < 0) row = 0;
        if (row > S - 1) row = S - 1;
        r[k] = q4[(size_t)row * DQ + col];
    }

#pragma unroll
    for (int i = 0; i < 8; i++) {
        const float cp = scp[i], cc = scc[i], cn = scn[i];
        float4 o;
        o.x = cp * r[i].x + cc * r[i + 1].x + cn * r[i + 2].x;
        o.y = cp * r[i].y + cc * r[i + 1].y + cn * r[i + 2].y;
        o.z = cp * r[i].z + cc * r[i + 1].z + cn * r[i + 2].z;
        o.w = cp * r[i].w + cc * r[i + 1].w + cn * r[i + 2].w;
        __stcs(&o4[(size_t)(s0 + i) * DQ + col], o);
    }
}

extern "C" void kernel_launch(void* const* d_in, const int* in_sizes, int n_in,
                              void* d_out, int out_size) {
    const float4* q4  = (const float4*)d_in[0];
    const float*  ent = (const float*)d_in[1];
    float4*       o4  = (float4*)d_out;

    dots_kernel<<<dim3(CCHUNKS, SGROUPS), TB_THREADS>>>(q4);
    coeff_kernel<<<1, 256>>>(ent);
    out_kernel<<<dim3(CCHUNKS, SGROUPS), TB_THREADS>>>(q4, o4);
}